// round 2
// baseline (speedup 1.0000x reference)
#include <cuda_runtime.h>
#include <math.h>

#define Bc   4
#define NQc  2048
#define NKc  2048
#define Dc   1024
#define Hc   8
#define DKc  128
#define DVc  128
#define DOc  1024
#define HBc  (Hc*Bc)
#define KT   (NKc/128)      // 16 k-tiles
#define STRD 132

typedef unsigned long long u64;

// Scratch (device globals: allocation-free)
__device__ float g_qh  [(size_t)Bc*NQc*Hc*DKc];
__device__ float g_kh  [(size_t)Bc*NKc*DKc];
__device__ float g_vh  [(size_t)Bc*NKc*DVc];
__device__ float g_outh[(size_t)Bc*NQc*Hc*DVc];
__device__ float g_tM  [(size_t)HBc*KT*NQc];
__device__ float g_tL  [(size_t)HBc*KT*NQc];
__device__ float g_rowM[(size_t)HBc*NQc];
__device__ float g_rowLi[(size_t)HBc*NQc];

// ---- packed fp32x2 helpers -------------------------------------------------
__device__ __forceinline__ u64 pk2(float lo, float hi){
    u64 r; asm("mov.b64 %0,{%1,%2};" : "=l"(r) : "f"(lo), "f"(hi)); return r;
}
__device__ __forceinline__ void fma2(u64 &d, u64 a, u64 b){
    asm("fma.rn.f32x2 %0,%1,%2,%0;" : "+l"(d) : "l"(a), "l"(b));
}
__device__ __forceinline__ float2 up2(u64 v){
    float2 f; asm("mov.b64 {%0,%1},%2;" : "=f"(f.x), "=f"(f.y) : "l"(v)); return f;
}

// 8x8 per-thread microkernel step: a from As[ty8..], b from Bs[tx8..]
__device__ __forceinline__ void mk_step(const float* __restrict__ As,
                                        const float* __restrict__ Bs,
                                        int ty8, int tx8, u64 acc[8][4]){
    float4 a0 = *(const float4*)(As + ty8);
    float4 a1 = *(const float4*)(As + ty8 + 4);
    u64 b0 = *(const u64*)(Bs + tx8);
    u64 b1 = *(const u64*)(Bs + tx8 + 2);
    u64 b2 = *(const u64*)(Bs + tx8 + 4);
    u64 b3 = *(const u64*)(Bs + tx8 + 6);
    float a[8] = {a0.x,a0.y,a0.z,a0.w,a1.x,a1.y,a1.z,a1.w};
#pragma unroll
    for (int i = 0; i < 8; i++){
        u64 ap = pk2(a[i], a[i]);
        fma2(acc[i][0], ap, b0);
        fma2(acc[i][1], ap, b1);
        fma2(acc[i][2], ap, b2);
        fma2(acc[i][3], ap, b3);
    }
}

#define TSTORE(buf, cgv, rv, v) { (buf)[((cgv)+0)*STRD+(rv)]=(v).x; (buf)[((cgv)+1)*STRD+(rv)]=(v).y; \
                                  (buf)[((cgv)+2)*STRD+(rv)]=(v).z; (buf)[((cgv)+3)*STRD+(rv)]=(v).w; }

// ---------------------------------------------------------------------------
// C[M,N] = A[M,K] @ W[N,K]^T + bias.  128x128 tile, BK=16, double-buffered.
// ---------------------------------------------------------------------------
__global__ void __launch_bounds__(256,2) gemm_bias_128(
    const float* __restrict__ A, const float* __restrict__ W,
    const float* __restrict__ bias, float* __restrict__ C,
    int M, int N, int K)
{
    __shared__ float sh[4*16*STRD];
    float* Ab[2] = {sh,              sh + 16*STRD};
    float* Wb[2] = {sh + 2*16*STRD,  sh + 3*16*STRD};

    const int tid = threadIdx.x, tx = tid & 15, ty = tid >> 4;
    const int m0 = blockIdx.y << 7, n0 = blockIdx.x << 7;
    const int r  = tid >> 2, cg = (tid & 3) << 2;

    const float* Ap  = A + (size_t)(m0 + r)      * K + cg;
    const float* Ap2 = A + (size_t)(m0 + r + 64) * K + cg;
    const float* Wp  = W + (size_t)(n0 + r)      * K + cg;
    const float* Wp2 = W + (size_t)(n0 + r + 64) * K + cg;

    u64 acc[8][4];
#pragma unroll
    for (int i=0;i<8;i++)
#pragma unroll
        for (int j=0;j<4;j++) acc[i][j] = 0ULL;

    float4 av0 = *(const float4*)Ap,  av1 = *(const float4*)Ap2;
    float4 wv0 = *(const float4*)Wp,  wv1 = *(const float4*)Wp2;
    TSTORE(Ab[0], cg, r,    av0); TSTORE(Ab[0], cg, r+64, av1);
    TSTORE(Wb[0], cg, r,    wv0); TSTORE(Wb[0], cg, r+64, wv1);
    __syncthreads();

    const int T = K >> 4;
    for (int t = 0; t < T; t++){
        if (t + 1 < T){
            av0 = *(const float4*)(Ap  + (t+1)*16);
            av1 = *(const float4*)(Ap2 + (t+1)*16);
            wv0 = *(const float4*)(Wp  + (t+1)*16);
            wv1 = *(const float4*)(Wp2 + (t+1)*16);
        }
        const float* As = Ab[t & 1];
        const float* Ws = Wb[t & 1];
#pragma unroll
        for (int kk = 0; kk < 16; kk++)
            mk_step(As + kk*STRD, Ws + kk*STRD, ty<<3, tx<<3, acc);
        if (t + 1 < T){
            float* Ad = Ab[(t+1)&1]; float* Wd = Wb[(t+1)&1];
            TSTORE(Ad, cg, r,    av0); TSTORE(Ad, cg, r+64, av1);
            TSTORE(Wd, cg, r,    wv0); TSTORE(Wd, cg, r+64, wv1);
        }
        __syncthreads();
    }

    float4 bv0 = *(const float4*)(bias + n0 + (tx<<3));
    float4 bv1 = *(const float4*)(bias + n0 + (tx<<3) + 4);
#pragma unroll
    for (int i = 0; i < 8; i++){
        float2 p0=up2(acc[i][0]), p1=up2(acc[i][1]), p2=up2(acc[i][2]), p3=up2(acc[i][3]);
        float4 o0 = {p0.x+bv0.x, p0.y+bv0.y, p1.x+bv0.z, p1.y+bv0.w};
        float4 o1 = {p2.x+bv1.x, p2.y+bv1.y, p3.x+bv1.z, p3.y+bv1.w};
        float* cp = C + (size_t)(m0 + (ty<<3) + i) * N + n0 + (tx<<3);
        *(float4*)cp = o0; *(float4*)(cp+4) = o1;
    }
}

// ---------------------------------------------------------------------------
// Scores tile: S[128q x 128k] = scale*(Qh @ Kh^T) + mask -> attn (raw),
// plus per-tile row max / sumexp into g_tM/g_tL.
// grid (NK/128, NQ/128, H*B)
// ---------------------------------------------------------------------------
__global__ void __launch_bounds__(256,2) scores2(
    const float* __restrict__ qh, const float* __restrict__ kh,
    const float* __restrict__ mask, float* __restrict__ attn,
    float* __restrict__ tM, float* __restrict__ tL)
{
    __shared__ float sh[4*16*STRD];
    float* Qb[2] = {sh,             sh + 16*STRD};
    float* Kb[2] = {sh + 2*16*STRD, sh + 3*16*STRD};

    const int tid = threadIdx.x, tx = tid & 15, ty = tid >> 4;
    const int k0 = blockIdx.x << 7, q0 = blockIdx.y << 7;
    const int bz = blockIdx.z, b = bz >> 3, h = bz & 7;
    const int r = tid >> 2, cg = (tid & 3) << 2;

    const float* Qp  = qh + (size_t)(b*NQc + q0 + r)      * Dc + h*DKc + cg;
    const float* Qp2 = qh + (size_t)(b*NQc + q0 + r + 64) * Dc + h*DKc + cg;
    const float* Kp  = kh + (size_t)(b*NKc + k0 + r)      * DKc + cg;
    const float* Kp2 = kh + (size_t)(b*NKc + k0 + r + 64) * DKc + cg;

    u64 acc[8][4];
#pragma unroll
    for (int i=0;i<8;i++)
#pragma unroll
        for (int j=0;j<4;j++) acc[i][j] = 0ULL;

    float4 av0 = *(const float4*)Qp,  av1 = *(const float4*)Qp2;
    float4 wv0 = *(const float4*)Kp,  wv1 = *(const float4*)Kp2;
    TSTORE(Qb[0], cg, r,    av0); TSTORE(Qb[0], cg, r+64, av1);
    TSTORE(Kb[0], cg, r,    wv0); TSTORE(Kb[0], cg, r+64, wv1);
    __syncthreads();

    const int T = DKc >> 4;   // 8
    for (int t = 0; t < T; t++){
        if (t + 1 < T){
            av0 = *(const float4*)(Qp  + (t+1)*16);
            av1 = *(const float4*)(Qp2 + (t+1)*16);
            wv0 = *(const float4*)(Kp  + (t+1)*16);
            wv1 = *(const float4*)(Kp2 + (t+1)*16);
        }
        const float* As = Qb[t & 1];
        const float* Ws = Kb[t & 1];
#pragma unroll
        for (int kk = 0; kk < 16; kk++)
            mk_step(As + kk*STRD, Ws + kk*STRD, ty<<3, tx<<3, acc);
        if (t + 1 < T){
            float* Ad = Qb[(t+1)&1]; float* Wd = Kb[(t+1)&1];
            TSTORE(Ad, cg, r,    av0); TSTORE(Ad, cg, r+64, av1);
            TSTORE(Wd, cg, r,    wv0); TSTORE(Wd, cg, r+64, wv1);
        }
        __syncthreads();
    }

    const float scale = 0.08838834764831845f;   // 1/sqrt(128)
    float* smm = sh;          // 128*16
    float* sml = sh + 2048;   // 128*16

#pragma unroll
    for (int i = 0; i < 8; i++){
        const int row  = q0 + (ty<<3) + i;
        const int col0 = k0 + (tx<<3);
        float2 p0=up2(acc[i][0]), p1=up2(acc[i][1]), p2=up2(acc[i][2]), p3=up2(acc[i][3]);
        const float* mp = mask + ((size_t)b*NQc + row) * NKc + col0;
        float4 mv0 = *(const float4*)mp;
        float4 mv1 = *(const float4*)(mp + 4);
        float s[8];
        s[0] = fmaf(p0.x, scale, mv0.x); s[1] = fmaf(p0.y, scale, mv0.y);
        s[2] = fmaf(p1.x, scale, mv0.z); s[3] = fmaf(p1.y, scale, mv0.w);
        s[4] = fmaf(p2.x, scale, mv1.x); s[5] = fmaf(p2.y, scale, mv1.y);
        s[6] = fmaf(p3.x, scale, mv1.z); s[7] = fmaf(p3.y, scale, mv1.w);
        float* ap = attn + ((size_t)(h*Bc + b)*NQc + row) * NKc + col0;
        float4 o0 = {s[0],s[1],s[2],s[3]}, o1 = {s[4],s[5],s[6],s[7]};
        *(float4*)ap = o0; *(float4*)(ap+4) = o1;
        float mx = s[0];
#pragma unroll
        for (int j = 1; j < 8; j++) mx = fmaxf(mx, s[j]);
        float le = 0.f;
#pragma unroll
        for (int j = 0; j < 8; j++) le += __expf(s[j] - mx);
        smm[(((ty<<3)+i)<<4) + tx] = mx;
        sml[(((ty<<3)+i)<<4) + tx] = le;
    }
    __syncthreads();
    if (tid < 128){
        float M = -1e30f;
#pragma unroll
        for (int j = 0; j < 16; j++) M = fmaxf(M, smm[(tid<<4)+j]);
        float L = 0.f;
#pragma unroll
        for (int j = 0; j < 16; j++) L += sml[(tid<<4)+j] * __expf(smm[(tid<<4)+j] - M);
        const int o = ((bz*KT) + blockIdx.x) * NQc + q0 + tid;
        tM[o] = M; tL[o] = L;
    }
}

// Combine per-tile stats -> per-row M, 1/L
__global__ void reduce_rows(const float* __restrict__ tM, const float* __restrict__ tL,
                            float* __restrict__ rowM, float* __restrict__ rowLi)
{
    int idx = blockIdx.x * blockDim.x + threadIdx.x;
    if (idx >= HBc*NQc) return;
    int bz = idx / NQc, row = idx % NQc;
    float M = -1e30f;
#pragma unroll
    for (int t = 0; t < KT; t++) M = fmaxf(M, tM[(bz*KT + t)*NQc + row]);
    float L = 0.f;
#pragma unroll
    for (int t = 0; t < KT; t++) L += tL[(bz*KT + t)*NQc + row] * __expf(tM[(bz*KT + t)*NQc + row] - M);
    rowM[idx] = M; rowLi[idx] = 1.0f / L;
}

// ---------------------------------------------------------------------------
// attv: re-read raw scores, normalize p (write back), outh = P @ V.
// grid (NQ/128, H*B)
// ---------------------------------------------------------------------------
__global__ void __launch_bounds__(256,2) attv2(
    const float* __restrict__ vh, float* __restrict__ attn,
    const float* __restrict__ rowM, const float* __restrict__ rowLi,
    float* __restrict__ outh)
{
    __shared__ float sh[4*16*STRD];
    __shared__ float Ms[128], Li[128];
    float* Pb[2] = {sh,             sh + 16*STRD};
    float* Vb[2] = {sh + 2*16*STRD, sh + 3*16*STRD};

    const int tid = threadIdx.x, tx = tid & 15, ty = tid >> 4;
    const int q0 = blockIdx.x << 7;
    const int bz = blockIdx.y, b = bz >> 3, h = bz & 7;
    const int r  = tid >> 2, cg = (tid & 3) << 2;
    const int rv = tid >> 5, cgv = (tid & 31) << 2;

    if (tid < 128){
        int gi = bz*NQc + q0 + tid;
        Ms[tid] = rowM[gi];
        Li[tid] = rowLi[gi];
    }
    __syncthreads();

    float* Aw  = attn + ((size_t)(h*Bc + b)*NQc + q0 + r)      * NKc + cg;
    float* Aw2 = attn + ((size_t)(h*Bc + b)*NQc + q0 + r + 64) * NKc + cg;
    const float* Vp  = vh + (size_t)(b*NKc + rv)     * DVc + cgv;
    const float* Vp2 = vh + (size_t)(b*NKc + rv + 8) * DVc + cgv;

    u64 acc[8][4];
#pragma unroll
    for (int i=0;i<8;i++)
#pragma unroll
        for (int j=0;j<4;j++) acc[i][j] = 0ULL;

    // preload tile 0 (normalize A, write back, stage transposed; V direct)
    {
        float4 s0 = *(const float4*)Aw, s1 = *(const float4*)Aw2;
        float m1 = Ms[r],    l1 = Li[r];
        float m2 = Ms[r+64], l2 = Li[r+64];
        float4 pA = { __expf(s0.x-m1)*l1, __expf(s0.y-m1)*l1, __expf(s0.z-m1)*l1, __expf(s0.w-m1)*l1 };
        float4 pB = { __expf(s1.x-m2)*l2, __expf(s1.y-m2)*l2, __expf(s1.z-m2)*l2, __expf(s1.w-m2)*l2 };
        *(float4*)Aw = pA; *(float4*)Aw2 = pB;
        TSTORE(Pb[0], cg, r, pA); TSTORE(Pb[0], cg, r+64, pB);
        float4 v0 = *(const float4*)Vp, v1 = *(const float4*)Vp2;
        *(float4*)&Vb[0][rv*STRD + cgv]     = v0;
        *(float4*)&Vb[0][(rv+8)*STRD + cgv] = v1;
    }
    __syncthreads();

    const int T = NKc >> 4;   // 128
    for (int t = 0; t < T; t++){
        float4 s0, s1, v0, v1;
        if (t + 1 < T){
            s0 = *(const float4*)(Aw  + (t+1)*16);
            s1 = *(const float4*)(Aw2 + (t+1)*16);
            v0 = *(const float4*)(Vp  + (size_t)(t+1)*16*DVc);
            v1 = *(const float4*)(Vp2 + (size_t)(t+1)*16*DVc);
        }
        const float* As = Pb[t & 1];
        const float* Ws = Vb[t & 1];
#pragma unroll
        for (int kk = 0; kk < 16; kk++)
            mk_step(As + kk*STRD, Ws + kk*STRD, ty<<3, tx<<3, acc);
        if (t + 1 < T){
            float m1 = Ms[r],    l1 = Li[r];
            float m2 = Ms[r+64], l2 = Li[r+64];
            float4 pA = { __expf(s0.x-m1)*l1, __expf(s0.y-m1)*l1, __expf(s0.z-m1)*l1, __expf(s0.w-m1)*l1 };
            float4 pB = { __expf(s1.x-m2)*l2, __expf(s1.y-m2)*l2, __expf(s1.z-m2)*l2, __expf(s1.w-m2)*l2 };
            *(float4*)(Aw  + (t+1)*16) = pA;
            *(float4*)(Aw2 + (t+1)*16) = pB;
            float* Pd = Pb[(t+1)&1]; float* Vd = Vb[(t+1)&1];
            TSTORE(Pd, cg, r, pA); TSTORE(Pd, cg, r+64, pB);
            *(float4*)&Vd[rv*STRD + cgv]     = v0;
            *(float4*)&Vd[(rv+8)*STRD + cgv] = v1;
        }
        __syncthreads();
    }

#pragma unroll
    for (int i = 0; i < 8; i++){
        const int row = q0 + (ty<<3) + i;
        float2 p0=up2(acc[i][0]), p1=up2(acc[i][1]), p2=up2(acc[i][2]), p3=up2(acc[i][3]);
        float4 o0 = {p0.x, p0.y, p1.x, p1.y};
        float4 o1 = {p2.x, p2.y, p3.x, p3.y};
        float* op = outh + (size_t)(b*NQc + row) * (Hc*DVc) + h*DVc + (tx<<3);
        *(float4*)op = o0; *(float4*)(op+4) = o1;
    }
}

// ---------------------------------------------------------------------------
extern "C" void kernel_launch(void* const* d_in, const int* in_sizes, int n_in,
                              void* d_out, int out_size)
{
    const float* q    = (const float*)d_in[0];
    const float* k    = (const float*)d_in[1];
    const float* v    = (const float*)d_in[2];
    const float* mask = (const float*)d_in[3];
    const float* Wq   = (const float*)d_in[4];
    const float* bq   = (const float*)d_in[5];
    const float* Wk   = (const float*)d_in[6];
    const float* bk   = (const float*)d_in[7];
    const float* Wv   = (const float*)d_in[8];
    const float* bv   = (const float*)d_in[9];
    const float* Wo   = (const float*)d_in[10];
    const float* bo   = (const float*)d_in[11];

    float* attn = (float*)d_out;                       // (H*B, NQ, NK)
    float* outp = attn + (size_t)Hc*Bc*NQc*NKc;        // (B, NQ, DO)

    float *qh,*kh,*vh,*outh,*tM,*tL,*rm,*rli;
    cudaGetSymbolAddress((void**)&qh,   g_qh);
    cudaGetSymbolAddress((void**)&kh,   g_kh);
    cudaGetSymbolAddress((void**)&vh,   g_vh);
    cudaGetSymbolAddress((void**)&outh, g_outh);
    cudaGetSymbolAddress((void**)&tM,   g_tM);
    cudaGetSymbolAddress((void**)&tL,   g_tL);
    cudaGetSymbolAddress((void**)&rm,   g_rowM);
    cudaGetSymbolAddress((void**)&rli,  g_rowLi);

    dim3 blk(256);
    const int Mr = Bc*NQc;   // 8192

    gemm_bias_128<<<dim3((Hc*DKc)/128, Mr/128), blk>>>(q, Wq, bq, qh, Mr, Hc*DKc, Dc);
    gemm_bias_128<<<dim3(DKc/128,      Mr/128), blk>>>(k, Wk, bk, kh, Mr, DKc, Dc);
    gemm_bias_128<<<dim3(DVc/128,      Mr/128), blk>>>(v, Wv, bv, vh, Mr, DVc, Dc);

    scores2<<<dim3(NKc/128, NQc/128, HBc), blk>>>(qh, kh, mask, attn, tM, tL);
    reduce_rows<<<(HBc*NQc + 255)/256, 256>>>(tM, tL, rm, rli);
    attv2<<<dim3(NQc/128, HBc), blk>>>(vh, attn, rm, rli, outh);

    gemm_bias_128<<<dim3(DOc/128, Mr/128), blk>>>(outh, Wo, bo, outp, Mr, DOc, Hc*DVc);
}

// round 3
// speedup vs baseline: 1.0013x; 1.0013x over previous
#include <cuda_runtime.h>
#include <math.h>

#define Bc   4
#define NQc  2048
#define NKc  2048
#define Dc   1024
#define Hc   8
#define DKc  128
#define DVc  128
#define DOc  1024
#define HBc  (Hc*Bc)
#define KT   (NKc/128)      // 16 k-tiles
#define STRD 132

typedef unsigned long long u64;

// Scratch (device globals: allocation-free)
__device__ float g_qh  [(size_t)Bc*NQc*Hc*DKc];
__device__ float g_kh  [(size_t)Bc*NKc*DKc];
__device__ float g_vh  [(size_t)Bc*NKc*DVc];
__device__ float g_outh[(size_t)Bc*NQc*Hc*DVc];
__device__ float g_tM  [(size_t)HBc*KT*NQc];
__device__ float g_tL  [(size_t)HBc*KT*NQc];
__device__ float g_rowM[(size_t)HBc*NQc];
__device__ float g_rowLi[(size_t)HBc*NQc];

// ---- packed fp32x2 helpers -------------------------------------------------
__device__ __forceinline__ u64 pk2(float lo, float hi){
    u64 r; asm("mov.b64 %0,{%1,%2};" : "=l"(r) : "f"(lo), "f"(hi)); return r;
}
__device__ __forceinline__ void fma2(u64 &d, u64 a, u64 b){
    asm("fma.rn.f32x2 %0,%1,%2,%0;" : "+l"(d) : "l"(a), "l"(b));
}
__device__ __forceinline__ float2 up2(u64 v){
    float2 f; asm("mov.b64 {%0,%1},%2;" : "=f"(f.x), "=f"(f.y) : "l"(v)); return f;
}

// 8x8 per-thread microkernel step: a from As[ty8..], b from Bs[tx8..]
__device__ __forceinline__ void mk_step(const float* __restrict__ As,
                                        const float* __restrict__ Bs,
                                        int ty8, int tx8, u64 acc[8][4]){
    float4 a0 = *(const float4*)(As + ty8);
    float4 a1 = *(const float4*)(As + ty8 + 4);
    u64 b0 = *(const u64*)(Bs + tx8);
    u64 b1 = *(const u64*)(Bs + tx8 + 2);
    u64 b2 = *(const u64*)(Bs + tx8 + 4);
    u64 b3 = *(const u64*)(Bs + tx8 + 6);
    float a[8] = {a0.x,a0.y,a0.z,a0.w,a1.x,a1.y,a1.z,a1.w};
#pragma unroll
    for (int i = 0; i < 8; i++){
        u64 ap = pk2(a[i], a[i]);
        fma2(acc[i][0], ap, b0);
        fma2(acc[i][1], ap, b1);
        fma2(acc[i][2], ap, b2);
        fma2(acc[i][3], ap, b3);
    }
}

#define TSTORE(buf, cgv, rv, v) { (buf)[((cgv)+0)*STRD+(rv)]=(v).x; (buf)[((cgv)+1)*STRD+(rv)]=(v).y; \
                                  (buf)[((cgv)+2)*STRD+(rv)]=(v).z; (buf)[((cgv)+3)*STRD+(rv)]=(v).w; }

// ---------------------------------------------------------------------------
// C[M,N] = A[M,K] @ W[N,K]^T + bias.  128x128 tile, BK=16, double-buffered.
// ---------------------------------------------------------------------------
__global__ void __launch_bounds__(256,2) gemm_bias_128(
    const float* __restrict__ A, const float* __restrict__ W,
    const float* __restrict__ bias, float* __restrict__ C,
    int M, int N, int K)
{
    __shared__ float sh[4*16*STRD];
    float* Ab[2] = {sh,              sh + 16*STRD};
    float* Wb[2] = {sh + 2*16*STRD,  sh + 3*16*STRD};

    const int tid = threadIdx.x, tx = tid & 15, ty = tid >> 4;
    const int m0 = blockIdx.y << 7, n0 = blockIdx.x << 7;
    const int r  = tid >> 2, cg = (tid & 3) << 2;

    const float* Ap  = A + (size_t)(m0 + r)      * K + cg;
    const float* Ap2 = A + (size_t)(m0 + r + 64) * K + cg;
    const float* Wp  = W + (size_t)(n0 + r)      * K + cg;
    const float* Wp2 = W + (size_t)(n0 + r + 64) * K + cg;

    u64 acc[8][4];
#pragma unroll
    for (int i=0;i<8;i++)
#pragma unroll
        for (int j=0;j<4;j++) acc[i][j] = 0ULL;

    float4 av0 = *(const float4*)Ap,  av1 = *(const float4*)Ap2;
    float4 wv0 = *(const float4*)Wp,  wv1 = *(const float4*)Wp2;
    TSTORE(Ab[0], cg, r,    av0); TSTORE(Ab[0], cg, r+64, av1);
    TSTORE(Wb[0], cg, r,    wv0); TSTORE(Wb[0], cg, r+64, wv1);
    __syncthreads();

    const int T = K >> 4;
    for (int t = 0; t < T; t++){
        if (t + 1 < T){
            av0 = *(const float4*)(Ap  + (t+1)*16);
            av1 = *(const float4*)(Ap2 + (t+1)*16);
            wv0 = *(const float4*)(Wp  + (t+1)*16);
            wv1 = *(const float4*)(Wp2 + (t+1)*16);
        }
        const float* As = Ab[t & 1];
        const float* Ws = Wb[t & 1];
#pragma unroll
        for (int kk = 0; kk < 16; kk++)
            mk_step(As + kk*STRD, Ws + kk*STRD, ty<<3, tx<<3, acc);
        if (t + 1 < T){
            float* Ad = Ab[(t+1)&1]; float* Wd = Wb[(t+1)&1];
            TSTORE(Ad, cg, r,    av0); TSTORE(Ad, cg, r+64, av1);
            TSTORE(Wd, cg, r,    wv0); TSTORE(Wd, cg, r+64, wv1);
        }
        __syncthreads();
    }

    float4 bv0 = *(const float4*)(bias + n0 + (tx<<3));
    float4 bv1 = *(const float4*)(bias + n0 + (tx<<3) + 4);
#pragma unroll
    for (int i = 0; i < 8; i++){
        float2 p0=up2(acc[i][0]), p1=up2(acc[i][1]), p2=up2(acc[i][2]), p3=up2(acc[i][3]);
        float4 o0 = {p0.x+bv0.x, p0.y+bv0.y, p1.x+bv0.z, p1.y+bv0.w};
        float4 o1 = {p2.x+bv1.x, p2.y+bv1.y, p3.x+bv1.z, p3.y+bv1.w};
        float* cp = C + (size_t)(m0 + (ty<<3) + i) * N + n0 + (tx<<3);
        *(float4*)cp = o0; *(float4*)(cp+4) = o1;
    }
}

// ---------------------------------------------------------------------------
// Scores tile: S[128q x 128k] = scale*(Qh @ Kh^T) + mask -> attn (raw),
// plus per-tile row max / sumexp into g_tM/g_tL.
// grid (NK/128, NQ/128, H*B)
// ---------------------------------------------------------------------------
__global__ void __launch_bounds__(256,2) scores2(
    const float* __restrict__ qh, const float* __restrict__ kh,
    const float* __restrict__ mask, float* __restrict__ attn,
    float* __restrict__ tM, float* __restrict__ tL)
{
    __shared__ float sh[4*16*STRD];
    float* Qb[2] = {sh,             sh + 16*STRD};
    float* Kb[2] = {sh + 2*16*STRD, sh + 3*16*STRD};

    const int tid = threadIdx.x, tx = tid & 15, ty = tid >> 4;
    const int k0 = blockIdx.x << 7, q0 = blockIdx.y << 7;
    const int bz = blockIdx.z, b = bz >> 3, h = bz & 7;
    const int r = tid >> 2, cg = (tid & 3) << 2;

    const float* Qp  = qh + (size_t)(b*NQc + q0 + r)      * Dc + h*DKc + cg;
    const float* Qp2 = qh + (size_t)(b*NQc + q0 + r + 64) * Dc + h*DKc + cg;
    const float* Kp  = kh + (size_t)(b*NKc + k0 + r)      * DKc + cg;
    const float* Kp2 = kh + (size_t)(b*NKc + k0 + r + 64) * DKc + cg;

    u64 acc[8][4];
#pragma unroll
    for (int i=0;i<8;i++)
#pragma unroll
        for (int j=0;j<4;j++) acc[i][j] = 0ULL;

    float4 av0 = *(const float4*)Qp,  av1 = *(const float4*)Qp2;
    float4 wv0 = *(const float4*)Kp,  wv1 = *(const float4*)Kp2;
    TSTORE(Qb[0], cg, r,    av0); TSTORE(Qb[0], cg, r+64, av1);
    TSTORE(Kb[0], cg, r,    wv0); TSTORE(Kb[0], cg, r+64, wv1);
    __syncthreads();

    const int T = DKc >> 4;   // 8
    for (int t = 0; t < T; t++){
        if (t + 1 < T){
            av0 = *(const float4*)(Qp  + (t+1)*16);
            av1 = *(const float4*)(Qp2 + (t+1)*16);
            wv0 = *(const float4*)(Kp  + (t+1)*16);
            wv1 = *(const float4*)(Kp2 + (t+1)*16);
        }
        const float* As = Qb[t & 1];
        const float* Ws = Kb[t & 1];
#pragma unroll
        for (int kk = 0; kk < 16; kk++)
            mk_step(As + kk*STRD, Ws + kk*STRD, ty<<3, tx<<3, acc);
        if (t + 1 < T){
            float* Ad = Qb[(t+1)&1]; float* Wd = Kb[(t+1)&1];
            TSTORE(Ad, cg, r,    av0); TSTORE(Ad, cg, r+64, av1);
            TSTORE(Wd, cg, r,    wv0); TSTORE(Wd, cg, r+64, wv1);
        }
        __syncthreads();
    }

    const float scale = 0.08838834764831845f;   // 1/sqrt(128)
    float* smm = sh;          // 128*16
    float* sml = sh + 2048;   // 128*16

#pragma unroll
    for (int i = 0; i < 8; i++){
        const int row  = q0 + (ty<<3) + i;
        const int col0 = k0 + (tx<<3);
        float2 p0=up2(acc[i][0]), p1=up2(acc[i][1]), p2=up2(acc[i][2]), p3=up2(acc[i][3]);
        const float* mp = mask + ((size_t)b*NQc + row) * NKc + col0;
        float4 mv0 = *(const float4*)mp;
        float4 mv1 = *(const float4*)(mp + 4);
        float s[8];
        s[0] = fmaf(p0.x, scale, mv0.x); s[1] = fmaf(p0.y, scale, mv0.y);
        s[2] = fmaf(p1.x, scale, mv0.z); s[3] = fmaf(p1.y, scale, mv0.w);
        s[4] = fmaf(p2.x, scale, mv1.x); s[5] = fmaf(p2.y, scale, mv1.y);
        s[6] = fmaf(p3.x, scale, mv1.z); s[7] = fmaf(p3.y, scale, mv1.w);
        float* ap = attn + ((size_t)(h*Bc + b)*NQc + row) * NKc + col0;
        float4 o0 = {s[0],s[1],s[2],s[3]}, o1 = {s[4],s[5],s[6],s[7]};
        *(float4*)ap = o0; *(float4*)(ap+4) = o1;
        float mx = s[0];
#pragma unroll
        for (int j = 1; j < 8; j++) mx = fmaxf(mx, s[j]);
        float le = 0.f;
#pragma unroll
        for (int j = 0; j < 8; j++) le += __expf(s[j] - mx);
        smm[(((ty<<3)+i)<<4) + tx] = mx;
        sml[(((ty<<3)+i)<<4) + tx] = le;
    }
    __syncthreads();
    if (tid < 128){
        float M = -1e30f;
#pragma unroll
        for (int j = 0; j < 16; j++) M = fmaxf(M, smm[(tid<<4)+j]);
        float L = 0.f;
#pragma unroll
        for (int j = 0; j < 16; j++) L += sml[(tid<<4)+j] * __expf(smm[(tid<<4)+j] - M);
        const int o = ((bz*KT) + blockIdx.x) * NQc + q0 + tid;
        tM[o] = M; tL[o] = L;
    }
}

// Combine per-tile stats -> per-row M, 1/L
__global__ void reduce_rows(const float* __restrict__ tM, const float* __restrict__ tL,
                            float* __restrict__ rowM, float* __restrict__ rowLi)
{
    int idx = blockIdx.x * blockDim.x + threadIdx.x;
    if (idx >= HBc*NQc) return;
    int bz = idx / NQc, row = idx % NQc;
    float M = -1e30f;
#pragma unroll
    for (int t = 0; t < KT; t++) M = fmaxf(M, tM[(bz*KT + t)*NQc + row]);
    float L = 0.f;
#pragma unroll
    for (int t = 0; t < KT; t++) L += tL[(bz*KT + t)*NQc + row] * __expf(tM[(bz*KT + t)*NQc + row] - M);
    rowM[idx] = M; rowLi[idx] = 1.0f / L;
}

// ---------------------------------------------------------------------------
// attv: re-read raw scores, normalize p (write back), outh = P @ V.
// grid (NQ/128, H*B)
// ---------------------------------------------------------------------------
__global__ void __launch_bounds__(256,2) attv2(
    const float* __restrict__ vh, float* __restrict__ attn,
    const float* __restrict__ rowM, const float* __restrict__ rowLi,
    float* __restrict__ outh)
{
    __shared__ float sh[4*16*STRD];
    __shared__ float Ms[128], Li[128];
    float* Pb[2] = {sh,             sh + 16*STRD};
    float* Vb[2] = {sh + 2*16*STRD, sh + 3*16*STRD};

    const int tid = threadIdx.x, tx = tid & 15, ty = tid >> 4;
    const int q0 = blockIdx.x << 7;
    const int bz = blockIdx.y, b = bz >> 3, h = bz & 7;
    const int r  = tid >> 2, cg = (tid & 3) << 2;
    const int rv = tid >> 5, cgv = (tid & 31) << 2;

    if (tid < 128){
        int gi = bz*NQc + q0 + tid;
        Ms[tid] = rowM[gi];
        Li[tid] = rowLi[gi];
    }
    __syncthreads();

    float* Aw  = attn + ((size_t)(h*Bc + b)*NQc + q0 + r)      * NKc + cg;
    float* Aw2 = attn + ((size_t)(h*Bc + b)*NQc + q0 + r + 64) * NKc + cg;
    const float* Vp  = vh + (size_t)(b*NKc + rv)     * DVc + cgv;
    const float* Vp2 = vh + (size_t)(b*NKc + rv + 8) * DVc + cgv;

    u64 acc[8][4];
#pragma unroll
    for (int i=0;i<8;i++)
#pragma unroll
        for (int j=0;j<4;j++) acc[i][j] = 0ULL;

    // preload tile 0 (normalize A, write back, stage transposed; V direct)
    {
        float4 s0 = *(const float4*)Aw, s1 = *(const float4*)Aw2;
        float m1 = Ms[r],    l1 = Li[r];
        float m2 = Ms[r+64], l2 = Li[r+64];
        float4 pA = { __expf(s0.x-m1)*l1, __expf(s0.y-m1)*l1, __expf(s0.z-m1)*l1, __expf(s0.w-m1)*l1 };
        float4 pB = { __expf(s1.x-m2)*l2, __expf(s1.y-m2)*l2, __expf(s1.z-m2)*l2, __expf(s1.w-m2)*l2 };
        *(float4*)Aw = pA; *(float4*)Aw2 = pB;
        TSTORE(Pb[0], cg, r, pA); TSTORE(Pb[0], cg, r+64, pB);
        float4 v0 = *(const float4*)Vp, v1 = *(const float4*)Vp2;
        *(float4*)&Vb[0][rv*STRD + cgv]     = v0;
        *(float4*)&Vb[0][(rv+8)*STRD + cgv] = v1;
    }
    __syncthreads();

    const int T = NKc >> 4;   // 128
    for (int t = 0; t < T; t++){
        float4 s0, s1, v0, v1;
        if (t + 1 < T){
            s0 = *(const float4*)(Aw  + (t+1)*16);
            s1 = *(const float4*)(Aw2 + (t+1)*16);
            v0 = *(const float4*)(Vp  + (size_t)(t+1)*16*DVc);
            v1 = *(const float4*)(Vp2 + (size_t)(t+1)*16*DVc);
        }
        const float* As = Pb[t & 1];
        const float* Ws = Vb[t & 1];
#pragma unroll
        for (int kk = 0; kk < 16; kk++)
            mk_step(As + kk*STRD, Ws + kk*STRD, ty<<3, tx<<3, acc);
        if (t + 1 < T){
            float m1 = Ms[r],    l1 = Li[r];
            float m2 = Ms[r+64], l2 = Li[r+64];
            float4 pA = { __expf(s0.x-m1)*l1, __expf(s0.y-m1)*l1, __expf(s0.z-m1)*l1, __expf(s0.w-m1)*l1 };
            float4 pB = { __expf(s1.x-m2)*l2, __expf(s1.y-m2)*l2, __expf(s1.z-m2)*l2, __expf(s1.w-m2)*l2 };
            *(float4*)(Aw  + (t+1)*16) = pA;
            *(float4*)(Aw2 + (t+1)*16) = pB;
            float* Pd = Pb[(t+1)&1]; float* Vd = Vb[(t+1)&1];
            TSTORE(Pd, cg, r, pA); TSTORE(Pd, cg, r+64, pB);
            *(float4*)&Vd[rv*STRD + cgv]     = v0;
            *(float4*)&Vd[(rv+8)*STRD + cgv] = v1;
        }
        __syncthreads();
    }

#pragma unroll
    for (int i = 0; i < 8; i++){
        const int row = q0 + (ty<<3) + i;
        float2 p0=up2(acc[i][0]), p1=up2(acc[i][1]), p2=up2(acc[i][2]), p3=up2(acc[i][3]);
        float4 o0 = {p0.x, p0.y, p1.x, p1.y};
        float4 o1 = {p2.x, p2.y, p3.x, p3.y};
        float* op = outh + (size_t)(b*NQc + row) * (Hc*DVc) + h*DVc + (tx<<3);
        *(float4*)op = o0; *(float4*)(op+4) = o1;
    }
}

// ---------------------------------------------------------------------------
extern "C" void kernel_launch(void* const* d_in, const int* in_sizes, int n_in,
                              void* d_out, int out_size)
{
    const float* q    = (const float*)d_in[0];
    const float* k    = (const float*)d_in[1];
    const float* v    = (const float*)d_in[2];
    const float* mask = (const float*)d_in[3];
    const float* Wq   = (const float*)d_in[4];
    const float* bq   = (const float*)d_in[5];
    const float* Wk   = (const float*)d_in[6];
    const float* bk   = (const float*)d_in[7];
    const float* Wv   = (const float*)d_in[8];
    const float* bv   = (const float*)d_in[9];
    const float* Wo   = (const float*)d_in[10];
    const float* bo   = (const float*)d_in[11];

    float* attn = (float*)d_out;                       // (H*B, NQ, NK)
    float* outp = attn + (size_t)Hc*Bc*NQc*NKc;        // (B, NQ, DO)

    float *qh,*kh,*vh,*outh,*tM,*tL,*rm,*rli;
    cudaGetSymbolAddress((void**)&qh,   g_qh);
    cudaGetSymbolAddress((void**)&kh,   g_kh);
    cudaGetSymbolAddress((void**)&vh,   g_vh);
    cudaGetSymbolAddress((void**)&outh, g_outh);
    cudaGetSymbolAddress((void**)&tM,   g_tM);
    cudaGetSymbolAddress((void**)&tL,   g_tL);
    cudaGetSymbolAddress((void**)&rm,   g_rowM);
    cudaGetSymbolAddress((void**)&rli,  g_rowLi);

    dim3 blk(256);
    const int Mr = Bc*NQc;   // 8192

    gemm_bias_128<<<dim3((Hc*DKc)/128, Mr/128), blk>>>(q, Wq, bq, qh, Mr, Hc*DKc, Dc);
    gemm_bias_128<<<dim3(DKc/128,      Mr/128), blk>>>(k, Wk, bk, kh, Mr, DKc, Dc);
    gemm_bias_128<<<dim3(DVc/128,      Mr/128), blk>>>(v, Wv, bv, vh, Mr, DVc, Dc);

    scores2<<<dim3(NKc/128, NQc/128, HBc), blk>>>(qh, kh, mask, attn, tM, tL);
    reduce_rows<<<(HBc*NQc + 255)/256, 256>>>(tM, tL, rm, rli);
    attv2<<<dim3(NQc/128, HBc), blk>>>(vh, attn, rm, rli, outh);

    gemm_bias_128<<<dim3(DOc/128, Mr/128), blk>>>(outh, Wo, bo, outp, Mr, DOc, Hc*DVc);
}

// round 6
// speedup vs baseline: 2.2487x; 2.2457x over previous
#include <cuda_runtime.h>
#include <cuda_bf16.h>
#include <math.h>
#include <stdint.h>

typedef unsigned int u32;

#define Bc   4
#define NQc  2048
#define NKc  2048
#define Dc   1024
#define Hc   8
#define DKc  128
#define DVc  128
#define DOc  1024
#define HBc  32
#define KTILES 16

__device__ float g_qh  [(size_t)Bc*NQc*Hc*DKc];
__device__ float g_kh  [(size_t)Bc*NKc*DKc];
__device__ float g_vh  [(size_t)Bc*NKc*DVc];
__device__ float g_vT  [(size_t)Bc*DVc*NKc];
__device__ float g_outh[(size_t)Bc*NQc*Hc*DVc];
__device__ float g_tM  [(size_t)HBc*KTILES*2*NQc];
__device__ float g_tL  [(size_t)HBc*KTILES*2*NQc];
__device__ float g_rowM[(size_t)HBc*NQc];
__device__ float g_rowLi[(size_t)HBc*NQc];

// ---------------- helpers ---------------------------------------------------
__device__ __forceinline__ u32 s2u(const void* p){
    u32 a; asm("{ .reg .u64 t; cvta.to.shared.u64 t, %1; cvt.u32.u64 %0, t; }"
               : "=r"(a) : "l"(p)); return a;
}
__device__ __forceinline__ u32 pkbf2(float a, float b){
    u32 ra = (u32)__bfloat16_as_ushort(__float2bfloat16(a));
    u32 rb = (u32)__bfloat16_as_ushort(__float2bfloat16(b));
    return ra | (rb << 16);
}
__device__ __forceinline__ float bres(float x){
    return x - __bfloat162float(__float2bfloat16(x));
}
__device__ __forceinline__ void ldmx4(u32* r, u32 addr){
    asm volatile("ldmatrix.sync.aligned.m8n8.x4.shared.b16 {%0,%1,%2,%3}, [%4];"
        : "=r"(r[0]), "=r"(r[1]), "=r"(r[2]), "=r"(r[3]) : "r"(addr));
}
__device__ __forceinline__ void mma16816(float* c, const u32* a, u32 b0, u32 b1){
    asm volatile("mma.sync.aligned.m16n8k16.row.col.f32.bf16.bf16.f32 "
        "{%0,%1,%2,%3}, {%4,%5,%6,%7}, {%8,%9}, {%0,%1,%2,%3};"
        : "+f"(c[0]), "+f"(c[1]), "+f"(c[2]), "+f"(c[3])
        : "r"(a[0]), "r"(a[1]), "r"(a[2]), "r"(a[3]), "r"(b0), "r"(b1));
}

// tile 128 rows x COLS cols fp32 (row stride ldA) -> bf16 hi/lo smem, row stride STRIDE (bf16)
template<int COLS, int STRIDE>
__device__ __forceinline__ void ldconv(const float* __restrict__ g, int ldA,
                                       char* smHi, char* smLo, int tid){
    const int PER = (128*COLS/4)/256;
#pragma unroll
    for (int i = 0; i < PER; i++){
        int idx = tid + i*256;
        int row = idx / (COLS/4);
        int c4  = (idx % (COLS/4))*4;
        float4 v = *(const float4*)(g + (size_t)row*ldA + c4);
        int off = (row*STRIDE + c4)*2;
        *(uint2*)(smHi+off) = make_uint2(pkbf2(v.x,v.y), pkbf2(v.z,v.w));
        *(uint2*)(smLo+off) = make_uint2(pkbf2(bres(v.x),bres(v.y)),
                                         pkbf2(bres(v.z),bres(v.w)));
    }
}

// One k-step (k=16): warp computes 32x64 using split bf16x3.
template<int SA, int SB>
__device__ __forceinline__ void wstep(u32 Ah, u32 Al, u32 Bh, u32 Bl,
                                      int ks, int warp_m, int warp_n, int lane,
                                      float c[2][8][4]){
    const int rsel = lane & 15, ksel = (lane >> 4) << 3;
    const int kb = ks*16 + ksel;
    u32 ah[2][4], al[2][4], bh[4][4], bl[4][4];
#pragma unroll
    for (int mt = 0; mt < 2; mt++){
        u32 off = (u32)((warp_m*32 + mt*16 + rsel)*SA + kb)*2;
        ldmx4(ah[mt], Ah + off);
        ldmx4(al[mt], Al + off);
    }
#pragma unroll
    for (int p = 0; p < 4; p++){
        u32 off = (u32)((warp_n*64 + p*16 + rsel)*SB + kb)*2;
        ldmx4(bh[p], Bh + off);
        ldmx4(bl[p], Bl + off);
    }
#pragma unroll
    for (int mt = 0; mt < 2; mt++)
#pragma unroll
        for (int nt = 0; nt < 8; nt++){
            int p = nt >> 1, s = nt & 1;
            u32 b0h = bh[p][s], b1h = bh[p][2+s];
            u32 b0l = bl[p][s], b1l = bl[p][2+s];
            mma16816(c[mt][nt], ah[mt], b0h, b1h);
            mma16816(c[mt][nt], ah[mt], b0l, b1l);
            mma16816(c[mt][nt], al[mt], b0h, b1h);
        }
}

// ---------------------------------------------------------------------------
// proj: C[M,N] = A[M,K] @ W[N,K]^T + bias. 128x128 CTA tile, KC=32 chunks.
// ---------------------------------------------------------------------------
#define PSTR 40
#define PTILE (128*PSTR*2)
__global__ void __launch_bounds__(256) proj_mma(
    const float* __restrict__ A, const float* __restrict__ W,
    const float* __restrict__ bias, float* __restrict__ C,
    int M, int N, int K)
{
    extern __shared__ char sm[];
    u32 sb = s2u(sm);
    const int tid = threadIdx.x, lane = tid & 31, wid = tid >> 5;
    const int warp_m = wid & 3, warp_n = wid >> 2;
    const int n0 = blockIdx.x << 7, m0 = blockIdx.y << 7;

    char* Ahp = sm;            char* Alp = sm + PTILE;
    char* Bhp = sm + 2*PTILE;  char* Blp = sm + 3*PTILE;
    const u32 Ah = sb, Al = sb + PTILE, Bh = sb + 2*PTILE, Bl = sb + 3*PTILE;

    float c[2][8][4];
#pragma unroll
    for (int i=0;i<2;i++) for (int j=0;j<8;j++) for (int q=0;q<4;q++) c[i][j][q]=0.f;

    for (int kc = 0; kc < K/32; kc++){
        ldconv<32,PSTR>(A + (size_t)m0*K + kc*32, K, Ahp, Alp, tid);
        ldconv<32,PSTR>(W + (size_t)n0*K + kc*32, K, Bhp, Blp, tid);
        __syncthreads();
#pragma unroll
        for (int ks = 0; ks < 2; ks++)
            wstep<PSTR,PSTR>(Ah, Al, Bh, Bl, ks, warp_m, warp_n, lane, c);
        __syncthreads();
    }

#pragma unroll
    for (int mt = 0; mt < 2; mt++)
#pragma unroll
        for (int rh = 0; rh < 2; rh++){
            int row = m0 + warp_m*32 + mt*16 + rh*8 + (lane >> 2);
#pragma unroll
            for (int nt = 0; nt < 8; nt++){
                int col = n0 + warp_n*64 + nt*8 + ((lane & 3) << 1);
                float2 o;
                o.x = c[mt][nt][rh*2+0] + __ldg(bias + col);
                o.y = c[mt][nt][rh*2+1] + __ldg(bias + col + 1);
                *(float2*)(C + (size_t)row*N + col) = o;
            }
        }
}

// ---------------------------------------------------------------------------
// scores: per (q-tile 128, hb): S = scale*(Q@K^T)+mask over 16 k-tiles.
// Raw S -> attn; per-row per-warp-half stats -> tM/tL (32 slots per row).
// ---------------------------------------------------------------------------
#define SSTR 136
#define STILE (128*SSTR*2)
__global__ void __launch_bounds__(256) scores_mma(
    const float* __restrict__ qh, const float* __restrict__ kh,
    const float* __restrict__ mask, float* __restrict__ attn,
    float* __restrict__ tM, float* __restrict__ tL)
{
    extern __shared__ char sm[];
    u32 sb = s2u(sm);
    const int tid = threadIdx.x, lane = tid & 31, wid = tid >> 5;
    const int warp_m = wid & 3, warp_n = wid >> 2;
    const int q0 = blockIdx.x << 7;
    const int hb = blockIdx.y, b = hb >> 3, h = hb & 7;

    char* Qhp = sm;            char* Qlp = sm + STILE;
    char* Khp = sm + 2*STILE;  char* Klp = sm + 3*STILE;
    const u32 Qh = sb, Ql = sb + STILE, Kh = sb + 2*STILE, Kl = sb + 3*STILE;

    const float* qbase = qh + (size_t)(b*NQc + q0)*Dc + h*DKc;
    const float* kbase = kh + (size_t)b*NKc*DKc;
    ldconv<128,SSTR>(qbase, Dc, Qhp, Qlp, tid);

    const float scale = 0.08838834764831845f;

    for (int kt = 0; kt < KTILES; kt++){
        __syncthreads();
        ldconv<128,SSTR>(kbase + (size_t)(kt*128)*DKc, DKc, Khp, Klp, tid);
        __syncthreads();

        float c[2][8][4];
#pragma unroll
        for (int i=0;i<2;i++) for (int j=0;j<8;j++) for (int q=0;q<4;q++) c[i][j][q]=0.f;
#pragma unroll
        for (int ks = 0; ks < 8; ks++)
            wstep<SSTR,SSTR>(Qh, Ql, Kh, Kl, ks, warp_m, warp_n, lane, c);

        // epilogue: scale + mask, write raw S, row stats
#pragma unroll
        for (int mt = 0; mt < 2; mt++)
#pragma unroll
            for (int rh = 0; rh < 2; rh++){
                int row = q0 + warp_m*32 + mt*16 + rh*8 + (lane >> 2);
                const float* mrow = mask + ((size_t)b*NQc + row)*NKc + kt*128;
                float* arow = attn + ((size_t)(h*Bc + b)*NQc + row)*NKc + kt*128;
                float mx = -1e30f, le = 0.f;
#pragma unroll
                for (int nt = 0; nt < 8; nt++){
                    int col = warp_n*64 + nt*8 + ((lane & 3) << 1);
                    float2 mv = *(const float2*)(mrow + col);
                    float s0 = fmaf(c[mt][nt][rh*2+0], scale, mv.x);
                    float s1 = fmaf(c[mt][nt][rh*2+1], scale, mv.y);
                    *(float2*)(arow + col) = make_float2(s0, s1);
                    float m2 = fmaxf(s0, s1);
                    float nm = fmaxf(mx, m2);
                    le = le*__expf(mx - nm) + __expf(s0 - nm) + __expf(s1 - nm);
                    mx = nm;
                }
#pragma unroll
                for (int off = 1; off <= 2; off <<= 1){
                    float mo = __shfl_xor_sync(0xFFFFFFFFu, mx, off);
                    float lo = __shfl_xor_sync(0xFFFFFFFFu, le, off);
                    float nm = fmaxf(mx, mo);
                    le = le*__expf(mx - nm) + lo*__expf(mo - nm);
                    mx = nm;
                }
                // store per-warp-half stats: slot = kt*2 + warp_n (32 slots/row)
                if ((lane & 3) == 0){
                    size_t o = ((size_t)hb*KTILES*2 + kt*2 + warp_n)*NQc + row;
                    tM[o] = mx; tL[o] = le;
                }
            }
    }
}

// per-row combine over 32 slots (16 tiles x 2 warp halves)
__global__ void reduce_rows(const float* __restrict__ tM, const float* __restrict__ tL,
                            float* __restrict__ rowM, float* __restrict__ rowLi)
{
    int idx = blockIdx.x * blockDim.x + threadIdx.x;
    if (idx >= HBc*NQc) return;
    int bz = idx / NQc, row = idx % NQc;
    float M = -1e30f;
#pragma unroll
    for (int t = 0; t < KTILES*2; t++)
        M = fmaxf(M, tM[(size_t)(bz*KTILES*2 + t)*NQc + row]);
    float L = 0.f;
#pragma unroll
    for (int t = 0; t < KTILES*2; t++)
        L += tL[(size_t)(bz*KTILES*2 + t)*NQc + row]
           * __expf(tM[(size_t)(bz*KTILES*2 + t)*NQc + row] - M);
    rowM[idx] = M; rowLi[idx] = 1.0f / L;
}

// vh [b,k,d] -> vT [b,d,k]
__global__ void transpose_v(const float* __restrict__ vh, float* __restrict__ vT){
    __shared__ float t[32][33];
    int b = blockIdx.z;
    int k0 = blockIdx.x*32, d0 = blockIdx.y*32;
    int x = threadIdx.x, y = threadIdx.y;
#pragma unroll
    for (int i = 0; i < 32; i += 8)
        t[y+i][x] = vh[(size_t)(b*NKc + k0 + y + i)*DVc + d0 + x];
    __syncthreads();
#pragma unroll
    for (int i = 0; i < 32; i += 8)
        vT[((size_t)b*DVc + d0 + y + i)*NKc + k0 + x] = t[x][y+i];
}

// ---------------------------------------------------------------------------
// attv: normalize P (write back), outh = P @ V via vT. acc over 16 k-tiles.
// ---------------------------------------------------------------------------
__global__ void __launch_bounds__(256) attv_mma(
    const float* __restrict__ vT, float* __restrict__ attn,
    const float* __restrict__ rowM, const float* __restrict__ rowLi,
    float* __restrict__ outh)
{
    extern __shared__ char sm[];
    __shared__ float Ms[128], Li[128];
    u32 sb = s2u(sm);
    const int tid = threadIdx.x, lane = tid & 31, wid = tid >> 5;
    const int warp_m = wid & 3, warp_n = wid >> 2;
    const int q0 = blockIdx.x << 7;
    const int hb = blockIdx.y, b = hb >> 3, h = hb & 7;

    char* Php = sm;            char* Plp = sm + STILE;
    char* Vhp = sm + 2*STILE;  char* Vlp = sm + 3*STILE;
    const u32 Ph = sb, Pl = sb + STILE, Vh = sb + 2*STILE, Vl = sb + 3*STILE;

    if (tid < 128){
        int gi = hb*NQc + q0 + tid;
        Ms[tid] = rowM[gi];
        Li[tid] = rowLi[gi];
    }
    __syncthreads();

    float* abase = attn + ((size_t)(h*Bc + b)*NQc + q0)*NKc;
    const float* vbase = vT + (size_t)b*DVc*NKc;

    float c[2][8][4];
#pragma unroll
    for (int i=0;i<2;i++) for (int j=0;j<8;j++) for (int q=0;q<4;q++) c[i][j][q]=0.f;

    for (int kt = 0; kt < KTILES; kt++){
        // normalize P chunk (128 x 128), write back, stage bf16 hi/lo
#pragma unroll
        for (int i = 0; i < 16; i++){
            int idx = tid + i*256;
            int row = idx >> 5, c4 = (idx & 31) << 2;
            float* ap = abase + (size_t)row*NKc + kt*128 + c4;
            float4 s = *(float4*)ap;
            float mm = Ms[row], li = Li[row];
            float4 p;
            p.x = __expf(s.x - mm)*li; p.y = __expf(s.y - mm)*li;
            p.z = __expf(s.z - mm)*li; p.w = __expf(s.w - mm)*li;
            *(float4*)ap = p;
            int off = (row*SSTR + c4)*2;
            *(uint2*)(Php+off) = make_uint2(pkbf2(p.x,p.y), pkbf2(p.z,p.w));
            *(uint2*)(Plp+off) = make_uint2(pkbf2(bres(p.x),bres(p.y)),
                                            pkbf2(bres(p.z),bres(p.w)));
        }
        ldconv<128,SSTR>(vbase + kt*128, NKc, Vhp, Vlp, tid);
        __syncthreads();
#pragma unroll
        for (int ks = 0; ks < 8; ks++)
            wstep<SSTR,SSTR>(Ph, Pl, Vh, Vl, ks, warp_m, warp_n, lane, c);
        __syncthreads();
    }

#pragma unroll
    for (int mt = 0; mt < 2; mt++)
#pragma unroll
        for (int rh = 0; rh < 2; rh++){
            int row = q0 + warp_m*32 + mt*16 + rh*8 + (lane >> 2);
            float* op = outh + (size_t)(b*NQc + row)*(Hc*DVc) + h*DVc;
#pragma unroll
            for (int nt = 0; nt < 8; nt++){
                int col = warp_n*64 + nt*8 + ((lane & 3) << 1);
                *(float2*)(op + col) = make_float2(c[mt][nt][rh*2+0], c[mt][nt][rh*2+1]);
            }
        }
}

// ---------------------------------------------------------------------------
extern "C" void kernel_launch(void* const* d_in, const int* in_sizes, int n_in,
                              void* d_out, int out_size)
{
    const float* q    = (const float*)d_in[0];
    const float* k    = (const float*)d_in[1];
    const float* v    = (const float*)d_in[2];
    const float* mask = (const float*)d_in[3];
    const float* Wq   = (const float*)d_in[4];
    const float* bq   = (const float*)d_in[5];
    const float* Wk   = (const float*)d_in[6];
    const float* bk   = (const float*)d_in[7];
    const float* Wv   = (const float*)d_in[8];
    const float* bv   = (const float*)d_in[9];
    const float* Wo   = (const float*)d_in[10];
    const float* bo   = (const float*)d_in[11];

    float* attn = (float*)d_out;
    float* outp = attn + (size_t)HBc*NQc*NKc;

    float *qh,*kh,*vh,*vT,*outh,*tM,*tL,*rm,*rli;
    cudaGetSymbolAddress((void**)&qh,   g_qh);
    cudaGetSymbolAddress((void**)&kh,   g_kh);
    cudaGetSymbolAddress((void**)&vh,   g_vh);
    cudaGetSymbolAddress((void**)&vT,   g_vT);
    cudaGetSymbolAddress((void**)&outh, g_outh);
    cudaGetSymbolAddress((void**)&tM,   g_tM);
    cudaGetSymbolAddress((void**)&tL,   g_tL);
    cudaGetSymbolAddress((void**)&rm,   g_rowM);
    cudaGetSymbolAddress((void**)&rli,  g_rowLi);

    const int PROJ_SM = 4*PTILE;           // 40960
    const int BIG_SM  = 4*STILE;           // 139264
    cudaFuncSetAttribute(scores_mma, cudaFuncAttributeMaxDynamicSharedMemorySize, BIG_SM);
    cudaFuncSetAttribute(attv_mma,   cudaFuncAttributeMaxDynamicSharedMemorySize, BIG_SM);

    dim3 blk(256);
    const int Mr = Bc*NQc;   // 8192

    proj_mma<<<dim3((Hc*DKc)/128, Mr/128), blk, PROJ_SM>>>(q, Wq, bq, qh, Mr, Hc*DKc, Dc);
    proj_mma<<<dim3(1,            Mr/128), blk, PROJ_SM>>>(k, Wk, bk, kh, Mr, DKc, Dc);
    proj_mma<<<dim3(1,            Mr/128), blk, PROJ_SM>>>(v, Wv, bv, vh, Mr, DVc, Dc);

    transpose_v<<<dim3(NKc/32, DVc/32, Bc), dim3(32,8)>>>(vh, vT);

    scores_mma<<<dim3(NQc/128, HBc), blk, BIG_SM>>>(qh, kh, mask, attn, tM, tL);
    reduce_rows<<<(HBc*NQc + 255)/256, 256>>>(tM, tL, rm, rli);
    attv_mma<<<dim3(NQc/128, HBc), blk, BIG_SM>>>(vT, attn, rm, rli, outh);

    proj_mma<<<dim3(DOc/128, Mr/128), blk, PROJ_SM>>>(outh, Wo, bo, outp, Mr, DOc, Hc*DVc);
}

// round 7
// speedup vs baseline: 2.7063x; 1.2035x over previous
#include <cuda_runtime.h>
#include <cuda_bf16.h>
#include <math.h>
#include <stdint.h>

typedef unsigned int u32;

#define Bc   4
#define NQc  2048
#define NKc  2048
#define Dc   1024
#define Hc   8
#define DKc  128
#define DVc  128
#define DOc  1024
#define HBc  32
#define KTILES 16

__device__ float g_qh  [(size_t)Bc*NQc*Hc*DKc];
__device__ float g_kh  [(size_t)Bc*NKc*DKc];
__device__ float g_vh  [(size_t)Bc*NKc*DVc];
__device__ float g_vT  [(size_t)Bc*DVc*NKc];
__device__ float g_outh[(size_t)Bc*NQc*Hc*DVc];
__device__ float g_tM  [(size_t)HBc*KTILES*2*NQc];
__device__ float g_tL  [(size_t)HBc*KTILES*2*NQc];
__device__ float g_rowM[(size_t)HBc*NQc];
__device__ float g_rowLi[(size_t)HBc*NQc];

// ---------------- helpers ---------------------------------------------------
__device__ __forceinline__ u32 s2u(const void* p){
    u32 a; asm("{ .reg .u64 t; cvta.to.shared.u64 t, %1; cvt.u32.u64 %0, t; }"
               : "=r"(a) : "l"(p)); return a;
}
__device__ __forceinline__ u32 pkbf2(float a, float b){
    u32 ra = (u32)__bfloat16_as_ushort(__float2bfloat16(a));
    u32 rb = (u32)__bfloat16_as_ushort(__float2bfloat16(b));
    return ra | (rb << 16);
}
__device__ __forceinline__ float bres(float x){
    return x - __bfloat162float(__float2bfloat16(x));
}
__device__ __forceinline__ void ldmx4(u32* r, u32 addr){
    asm volatile("ldmatrix.sync.aligned.m8n8.x4.shared.b16 {%0,%1,%2,%3}, [%4];"
        : "=r"(r[0]), "=r"(r[1]), "=r"(r[2]), "=r"(r[3]) : "r"(addr));
}
__device__ __forceinline__ void mma16816(float* c, const u32* a, u32 b0, u32 b1){
    asm volatile("mma.sync.aligned.m16n8k16.row.col.f32.bf16.bf16.f32 "
        "{%0,%1,%2,%3}, {%4,%5,%6,%7}, {%8,%9}, {%0,%1,%2,%3};"
        : "+f"(c[0]), "+f"(c[1]), "+f"(c[2]), "+f"(c[3])
        : "r"(a[0]), "r"(a[1]), "r"(a[2]), "r"(a[3]), "r"(b0), "r"(b1));
}

// ---- split load/convert: 128 rows x COLS fp32 -> bf16 hi/lo smem -----------
template<int COLS>
__device__ __forceinline__ void loadregs(const float* __restrict__ g, int ldA,
                                         float4* pre, int tid){
    const int PER = (128*COLS/4)/256;
#pragma unroll
    for (int i = 0; i < PER; i++){
        int idx = tid + i*256;
        int row = idx / (COLS/4);
        int c4  = (idx % (COLS/4))*4;
        pre[i] = *(const float4*)(g + (size_t)row*ldA + c4);
    }
}
template<int COLS, int STRIDE>
__device__ __forceinline__ void convert(const float4* pre, char* smHi, char* smLo, int tid){
    const int PER = (128*COLS/4)/256;
#pragma unroll
    for (int i = 0; i < PER; i++){
        int idx = tid + i*256;
        int row = idx / (COLS/4);
        int c4  = (idx % (COLS/4))*4;
        float4 v = pre[i];
        int off = (row*STRIDE + c4)*2;
        *(uint2*)(smHi+off) = make_uint2(pkbf2(v.x,v.y), pkbf2(v.z,v.w));
        *(uint2*)(smLo+off) = make_uint2(pkbf2(bres(v.x),bres(v.y)),
                                         pkbf2(bres(v.z),bres(v.w)));
    }
}
template<int COLS, int STRIDE>
__device__ __forceinline__ void ldconv(const float* __restrict__ g, int ldA,
                                       char* smHi, char* smLo, int tid){
    const int PER = (128*COLS/4)/256;
#pragma unroll
    for (int i = 0; i < PER; i++){
        int idx = tid + i*256;
        int row = idx / (COLS/4);
        int c4  = (idx % (COLS/4))*4;
        float4 v = *(const float4*)(g + (size_t)row*ldA + c4);
        int off = (row*STRIDE + c4)*2;
        *(uint2*)(smHi+off) = make_uint2(pkbf2(v.x,v.y), pkbf2(v.z,v.w));
        *(uint2*)(smLo+off) = make_uint2(pkbf2(bres(v.x),bres(v.y)),
                                         pkbf2(bres(v.z),bres(v.w)));
    }
}

// One k-step (k=16): warp computes 32x64 using split bf16x3.
template<int SA, int SB>
__device__ __forceinline__ void wstep(u32 Ah, u32 Al, u32 Bh, u32 Bl,
                                      int ks, int warp_m, int warp_n, int lane,
                                      float c[2][8][4]){
    const int rsel = lane & 15, ksel = (lane >> 4) << 3;
    const int kb = ks*16 + ksel;
    u32 ah[2][4], al[2][4], bh[4][4], bl[4][4];
#pragma unroll
    for (int mt = 0; mt < 2; mt++){
        u32 off = (u32)((warp_m*32 + mt*16 + rsel)*SA + kb)*2;
        ldmx4(ah[mt], Ah + off);
        ldmx4(al[mt], Al + off);
    }
#pragma unroll
    for (int p = 0; p < 4; p++){
        u32 off = (u32)((warp_n*64 + p*16 + rsel)*SB + kb)*2;
        ldmx4(bh[p], Bh + off);
        ldmx4(bl[p], Bl + off);
    }
#pragma unroll
    for (int mt = 0; mt < 2; mt++)
#pragma unroll
        for (int nt = 0; nt < 8; nt++){
            int p = nt >> 1, s = nt & 1;
            u32 b0h = bh[p][s], b1h = bh[p][2+s];
            u32 b0l = bl[p][s], b1l = bl[p][2+s];
            mma16816(c[mt][nt], ah[mt], b0h, b1h);
            mma16816(c[mt][nt], ah[mt], b0l, b1l);
            mma16816(c[mt][nt], al[mt], b0h, b1h);
        }
}

// ---------------------------------------------------------------------------
// proj: C[M,N] = A[M,K] @ W[N,K]^T + bias. 128x128 CTA tile, K chunks of 64,
// register-prefetched.
// ---------------------------------------------------------------------------
#define PSTR 72
#define PTILE (128*PSTR*2)
__global__ void __launch_bounds__(256) proj_mma(
    const float* __restrict__ A, const float* __restrict__ W,
    const float* __restrict__ bias, float* __restrict__ C,
    int M, int N, int K)
{
    extern __shared__ char sm[];
    u32 sb = s2u(sm);
    const int tid = threadIdx.x, lane = tid & 31, wid = tid >> 5;
    const int warp_m = wid & 3, warp_n = wid >> 2;
    const int n0 = blockIdx.x << 7, m0 = blockIdx.y << 7;

    char* Ahp = sm;            char* Alp = sm + PTILE;
    char* Bhp = sm + 2*PTILE;  char* Blp = sm + 3*PTILE;
    const u32 Ah = sb, Al = sb + PTILE, Bh = sb + 2*PTILE, Bl = sb + 3*PTILE;

    float c[2][8][4];
#pragma unroll
    for (int i=0;i<2;i++) for (int j=0;j<8;j++) for (int q=0;q<4;q++) c[i][j][q]=0.f;

    float4 preA[8], preW[8];
    loadregs<64>(A + (size_t)m0*K, K, preA, tid);
    loadregs<64>(W + (size_t)n0*K, K, preW, tid);

    const int NC = K/64;
    for (int kc = 0; kc < NC; kc++){
        convert<64,PSTR>(preA, Ahp, Alp, tid);
        convert<64,PSTR>(preW, Bhp, Blp, tid);
        __syncthreads();
        if (kc + 1 < NC){
            loadregs<64>(A + (size_t)m0*K + (kc+1)*64, K, preA, tid);
            loadregs<64>(W + (size_t)n0*K + (kc+1)*64, K, preW, tid);
        }
#pragma unroll
        for (int ks = 0; ks < 4; ks++)
            wstep<PSTR,PSTR>(Ah, Al, Bh, Bl, ks, warp_m, warp_n, lane, c);
        __syncthreads();
    }

#pragma unroll
    for (int mt = 0; mt < 2; mt++)
#pragma unroll
        for (int rh = 0; rh < 2; rh++){
            int row = m0 + warp_m*32 + mt*16 + rh*8 + (lane >> 2);
#pragma unroll
            for (int nt = 0; nt < 8; nt++){
                int col = n0 + warp_n*64 + nt*8 + ((lane & 3) << 1);
                float2 o;
                o.x = c[mt][nt][rh*2+0] + __ldg(bias + col);
                o.y = c[mt][nt][rh*2+1] + __ldg(bias + col + 1);
                *(float2*)(C + (size_t)row*N + col) = o;
            }
        }
}

// ---------------------------------------------------------------------------
// scores: per (q-tile 128, hb): S = scale*(Q@K^T)+mask over 16 k-tiles.
// K tiles register-prefetched. Raw S -> attn; per-warp-half stats -> tM/tL.
// ---------------------------------------------------------------------------
#define SSTR 136
#define STILE (128*SSTR*2)
__global__ void __launch_bounds__(256) scores_mma(
    const float* __restrict__ qh, const float* __restrict__ kh,
    const float* __restrict__ mask, float* __restrict__ attn,
    float* __restrict__ tM, float* __restrict__ tL)
{
    extern __shared__ char sm[];
    u32 sb = s2u(sm);
    const int tid = threadIdx.x, lane = tid & 31, wid = tid >> 5;
    const int warp_m = wid & 3, warp_n = wid >> 2;
    const int q0 = blockIdx.x << 7;
    const int hb = blockIdx.y, b = hb >> 3, h = hb & 7;

    char* Qhp = sm;            char* Qlp = sm + STILE;
    char* Khp = sm + 2*STILE;  char* Klp = sm + 3*STILE;
    const u32 Qh = sb, Ql = sb + STILE, Kh = sb + 2*STILE, Kl = sb + 3*STILE;

    const float* qbase = qh + (size_t)(b*NQc + q0)*Dc + h*DKc;
    const float* kbase = kh + (size_t)b*NKc*DKc;
    ldconv<128,SSTR>(qbase, Dc, Qhp, Qlp, tid);

    float4 preK[16];
    loadregs<128>(kbase, DKc, preK, tid);

    const float scale = 0.08838834764831845f;

    for (int kt = 0; kt < KTILES; kt++){
        convert<128,SSTR>(preK, Khp, Klp, tid);
        __syncthreads();
        if (kt + 1 < KTILES)
            loadregs<128>(kbase + (size_t)((kt+1)*128)*DKc, DKc, preK, tid);

        float c[2][8][4];
#pragma unroll
        for (int i=0;i<2;i++) for (int j=0;j<8;j++) for (int q=0;q<4;q++) c[i][j][q]=0.f;
#pragma unroll
        for (int ks = 0; ks < 8; ks++)
            wstep<SSTR,SSTR>(Qh, Ql, Kh, Kl, ks, warp_m, warp_n, lane, c);

        // epilogue: scale + mask, write raw S, row stats
#pragma unroll
        for (int mt = 0; mt < 2; mt++)
#pragma unroll
            for (int rh = 0; rh < 2; rh++){
                int row = q0 + warp_m*32 + mt*16 + rh*8 + (lane >> 2);
                const float* mrow = mask + ((size_t)b*NQc + row)*NKc + kt*128;
                float* arow = attn + ((size_t)(h*Bc + b)*NQc + row)*NKc + kt*128;
                float mx = -1e30f, le = 0.f;
#pragma unroll
                for (int nt = 0; nt < 8; nt++){
                    int col = warp_n*64 + nt*8 + ((lane & 3) << 1);
                    float2 mv = *(const float2*)(mrow + col);
                    float s0 = fmaf(c[mt][nt][rh*2+0], scale, mv.x);
                    float s1 = fmaf(c[mt][nt][rh*2+1], scale, mv.y);
                    *(float2*)(arow + col) = make_float2(s0, s1);
                    float m2 = fmaxf(s0, s1);
                    float nm = fmaxf(mx, m2);
                    le = le*__expf(mx - nm) + __expf(s0 - nm) + __expf(s1 - nm);
                    mx = nm;
                }
#pragma unroll
                for (int off = 1; off <= 2; off <<= 1){
                    float mo = __shfl_xor_sync(0xFFFFFFFFu, mx, off);
                    float lo = __shfl_xor_sync(0xFFFFFFFFu, le, off);
                    float nm = fmaxf(mx, mo);
                    le = le*__expf(mx - nm) + lo*__expf(mo - nm);
                    mx = nm;
                }
                if ((lane & 3) == 0){
                    size_t o = ((size_t)hb*KTILES*2 + kt*2 + warp_n)*NQc + row;
                    tM[o] = mx; tL[o] = le;
                }
            }
        __syncthreads();
    }
}

// per-row combine over 32 slots (16 tiles x 2 warp halves)
__global__ void reduce_rows(const float* __restrict__ tM, const float* __restrict__ tL,
                            float* __restrict__ rowM, float* __restrict__ rowLi)
{
    int idx = blockIdx.x * blockDim.x + threadIdx.x;
    if (idx >= HBc*NQc) return;
    int bz = idx / NQc, row = idx % NQc;
    float M = -1e30f;
#pragma unroll
    for (int t = 0; t < KTILES*2; t++)
        M = fmaxf(M, tM[(size_t)(bz*KTILES*2 + t)*NQc + row]);
    float L = 0.f;
#pragma unroll
    for (int t = 0; t < KTILES*2; t++)
        L += tL[(size_t)(bz*KTILES*2 + t)*NQc + row]
           * __expf(tM[(size_t)(bz*KTILES*2 + t)*NQc + row] - M);
    rowM[idx] = M; rowLi[idx] = 1.0f / L;
}

// vh [b,k,d] -> vT [b,d,k]
__global__ void transpose_v(const float* __restrict__ vh, float* __restrict__ vT){
    __shared__ float t[32][33];
    int b = blockIdx.z;
    int k0 = blockIdx.x*32, d0 = blockIdx.y*32;
    int x = threadIdx.x, y = threadIdx.y;
#pragma unroll
    for (int i = 0; i < 32; i += 8)
        t[y+i][x] = vh[(size_t)(b*NKc + k0 + y + i)*DVc + d0 + x];
    __syncthreads();
#pragma unroll
    for (int i = 0; i < 32; i += 8)
        vT[((size_t)b*DVc + d0 + y + i)*NKc + k0 + x] = t[x][y+i];
}

// ---------------------------------------------------------------------------
// attv: normalize P (write back), outh = P @ V via vT. P register-prefetched.
// ---------------------------------------------------------------------------
__global__ void __launch_bounds__(256) attv_mma(
    const float* __restrict__ vT, float* __restrict__ attn,
    const float* __restrict__ rowM, const float* __restrict__ rowLi,
    float* __restrict__ outh)
{
    extern __shared__ char sm[];
    __shared__ float Ms[128], Li[128];
    u32 sb = s2u(sm);
    const int tid = threadIdx.x, lane = tid & 31, wid = tid >> 5;
    const int warp_m = wid & 3, warp_n = wid >> 2;
    const int q0 = blockIdx.x << 7;
    const int hb = blockIdx.y, b = hb >> 3, h = hb & 7;

    char* Php = sm;            char* Plp = sm + STILE;
    char* Vhp = sm + 2*STILE;  char* Vlp = sm + 3*STILE;
    const u32 Ph = sb, Pl = sb + STILE, Vh = sb + 2*STILE, Vl = sb + 3*STILE;

    if (tid < 128){
        int gi = hb*NQc + q0 + tid;
        Ms[tid] = rowM[gi];
        Li[tid] = rowLi[gi];
    }

    float* abase = attn + ((size_t)(h*Bc + b)*NQc + q0)*NKc;
    const float* vbase = vT + (size_t)b*DVc*NKc;

    float4 preP[16];
    loadregs<128>(abase, NKc, preP, tid);
    __syncthreads();

    float c[2][8][4];
#pragma unroll
    for (int i=0;i<2;i++) for (int j=0;j<8;j++) for (int q=0;q<4;q++) c[i][j][q]=0.f;

    for (int kt = 0; kt < KTILES; kt++){
        // normalize prefetched P chunk, write back, stage bf16 hi/lo
#pragma unroll
        for (int i = 0; i < 16; i++){
            int idx = tid + i*256;
            int row = idx >> 5, c4 = (idx & 31) << 2;
            float4 s = preP[i];
            float mm = Ms[row], li = Li[row];
            float4 p;
            p.x = __expf(s.x - mm)*li; p.y = __expf(s.y - mm)*li;
            p.z = __expf(s.z - mm)*li; p.w = __expf(s.w - mm)*li;
            *(float4*)(abase + (size_t)row*NKc + kt*128 + c4) = p;
            int off = (row*SSTR + c4)*2;
            *(uint2*)(Php+off) = make_uint2(pkbf2(p.x,p.y), pkbf2(p.z,p.w));
            *(uint2*)(Plp+off) = make_uint2(pkbf2(bres(p.x),bres(p.y)),
                                            pkbf2(bres(p.z),bres(p.w)));
        }
        ldconv<128,SSTR>(vbase + kt*128, NKc, Vhp, Vlp, tid);
        __syncthreads();
        if (kt + 1 < KTILES)
            loadregs<128>(abase + (kt+1)*128, NKc, preP, tid);
#pragma unroll
        for (int ks = 0; ks < 8; ks++)
            wstep<SSTR,SSTR>(Ph, Pl, Vh, Vl, ks, warp_m, warp_n, lane, c);
        __syncthreads();
    }

#pragma unroll
    for (int mt = 0; mt < 2; mt++)
#pragma unroll
        for (int rh = 0; rh < 2; rh++){
            int row = q0 + warp_m*32 + mt*16 + rh*8 + (lane >> 2);
            float* op = outh + (size_t)(b*NQc + row)*(Hc*DVc) + h*DVc;
#pragma unroll
            for (int nt = 0; nt < 8; nt++){
                int col = warp_n*64 + nt*8 + ((lane & 3) << 1);
                *(float2*)(op + col) = make_float2(c[mt][nt][rh*2+0], c[mt][nt][rh*2+1]);
            }
        }
}

// ---------------------------------------------------------------------------
extern "C" void kernel_launch(void* const* d_in, const int* in_sizes, int n_in,
                              void* d_out, int out_size)
{
    const float* q    = (const float*)d_in[0];
    const float* k    = (const float*)d_in[1];
    const float* v    = (const float*)d_in[2];
    const float* mask = (const float*)d_in[3];
    const float* Wq   = (const float*)d_in[4];
    const float* bq   = (const float*)d_in[5];
    const float* Wk   = (const float*)d_in[6];
    const float* bk   = (const float*)d_in[7];
    const float* Wv   = (const float*)d_in[8];
    const float* bv   = (const float*)d_in[9];
    const float* Wo   = (const float*)d_in[10];
    const float* bo   = (const float*)d_in[11];

    float* attn = (float*)d_out;
    float* outp = attn + (size_t)HBc*NQc*NKc;

    float *qh,*kh,*vh,*vT,*outh,*tM,*tL,*rm,*rli;
    cudaGetSymbolAddress((void**)&qh,   g_qh);
    cudaGetSymbolAddress((void**)&kh,   g_kh);
    cudaGetSymbolAddress((void**)&vh,   g_vh);
    cudaGetSymbolAddress((void**)&vT,   g_vT);
    cudaGetSymbolAddress((void**)&outh, g_outh);
    cudaGetSymbolAddress((void**)&tM,   g_tM);
    cudaGetSymbolAddress((void**)&tL,   g_tL);
    cudaGetSymbolAddress((void**)&rm,   g_rowM);
    cudaGetSymbolAddress((void**)&rli,  g_rowLi);

    const int PROJ_SM = 4*PTILE;           // 73728
    const int BIG_SM  = 4*STILE;           // 139264
    cudaFuncSetAttribute(proj_mma,   cudaFuncAttributeMaxDynamicSharedMemorySize, PROJ_SM);
    cudaFuncSetAttribute(scores_mma, cudaFuncAttributeMaxDynamicSharedMemorySize, BIG_SM);
    cudaFuncSetAttribute(attv_mma,   cudaFuncAttributeMaxDynamicSharedMemorySize, BIG_SM);

    dim3 blk(256);
    const int Mr = Bc*NQc;   // 8192

    proj_mma<<<dim3((Hc*DKc)/128, Mr/128), blk, PROJ_SM>>>(q, Wq, bq, qh, Mr, Hc*DKc, Dc);
    proj_mma<<<dim3(1,            Mr/128), blk, PROJ_SM>>>(k, Wk, bk, kh, Mr, DKc, Dc);
    proj_mma<<<dim3(1,            Mr/128), blk, PROJ_SM>>>(v, Wv, bv, vh, Mr, DVc, Dc);

    transpose_v<<<dim3(NKc/32, DVc/32, Bc), dim3(32,8)>>>(vh, vT);

    scores_mma<<<dim3(NQc/128, HBc), blk, BIG_SM>>>(qh, kh, mask, attn, tM, tL);
    reduce_rows<<<(HBc*NQc + 255)/256, 256>>>(tM, tL, rm, rli);
    attv_mma<<<dim3(NQc/128, HBc), blk, BIG_SM>>>(vT, attn, rm, rli, outh);

    proj_mma<<<dim3(DOc/128, Mr/128), blk, PROJ_SM>>>(outh, Wo, bo, outp, Mr, DOc, Hc*DVc);
}